// round 15
// baseline (speedup 1.0000x reference)
#include <cuda_runtime.h>
#include <cuda_bf16.h>
#include <cuda_fp16.h>
#include <cstdint>

// ---------------------------------------------------------------------------
// Problem constants
// ---------------------------------------------------------------------------
#define NN      20000
#define EE      160000
#define ETOT    (EE + NN)
#define IN_CH   128
#define H1      36
#define C1      36
#define HID     (H1 * C1)   // 1296
#define OUT_CH  128
#define K1P     (IN_CH / 2)   // 64 pairs
#define HIDP    (HID / 2)     // 648 pairs
#define K2P     (HID / 2)     // 648 pairs
#define K2PAD   672           // padded pairs (1344 elems = 84 * 16)

// ---------------------------------------------------------------------------
// Device scratch
// ---------------------------------------------------------------------------
__device__ __align__(16) unsigned int g_h1p[(size_t)NN * HIDP];       // h1 fp16 pairs (52MB)
__device__ __align__(16) float g_h2[(size_t)NN * OUT_CH];             // out1 @ W2 (fp32)
__device__ __align__(16) unsigned int g_xp[(size_t)NN * K1P];         // x fp16 pairs [M][64]
__device__ __align__(16) unsigned int g_w1[(size_t)HID * K1P];        // W1^T fp16 [1296][64]
__device__ __align__(16) unsigned int g_w2[(size_t)OUT_CH * K2PAD];   // W2^T fp16 [128][672]
__device__ __align__(16) unsigned int g_o1p[(size_t)NN * K2PAD];      // relu(agg1) fp16 [M][672]
__device__ __align__(16) float g_as1[NN * H1];
__device__ __align__(16) float g_ad1[NN * H1];
__device__ __align__(16) float g_as2[NN];
__device__ __align__(16) float g_ad2[NN];
__device__ int g_hist[NN];
__device__ int g_rowptr[NN + 1];
__device__ int g_cursor[NN];
__device__ int g_srt_src[ETOT];

// ---------------------------------------------------------------------------
// fp16 helpers
// ---------------------------------------------------------------------------
__device__ __forceinline__ uint32_t pack_h16(float a, float b) {
    __half2 t = __floats2half2_rn(a, b);    // .x = a (low half)
    return *reinterpret_cast<uint32_t*>(&t);
}
__device__ __forceinline__ float2 unpack_h16(uint32_t p) {
    __half2 t = *reinterpret_cast<__half2*>(&p);
    return __half22float2(t);
}

__device__ __forceinline__ void mma_f16(float* c,
                                        uint32_t a0, uint32_t a1,
                                        uint32_t a2, uint32_t a3,
                                        uint32_t b0, uint32_t b1) {
    asm volatile(
        "mma.sync.aligned.m16n8k16.row.col.f32.f16.f16.f32 "
        "{%0,%1,%2,%3}, {%4,%5,%6,%7}, {%8,%9}, {%0,%1,%2,%3};\n"
        : "+f"(c[0]), "+f"(c[1]), "+f"(c[2]), "+f"(c[3])
        : "r"(a0), "r"(a1), "r"(a2), "r"(a3), "r"(b0), "r"(b1));
}

__device__ __forceinline__ void ldsm_x4(uint32_t* r, uint32_t addr) {
    asm volatile(
        "ldmatrix.sync.aligned.m8n8.x4.shared.b16 {%0,%1,%2,%3}, [%4];"
        : "=r"(r[0]), "=r"(r[1]), "=r"(r[2]), "=r"(r[3]) : "r"(addr));
}

__device__ __forceinline__ void cp_async16(uint32_t dst, const void* src, bool pred) {
    int sz = pred ? 16 : 0;
    asm volatile("cp.async.ca.shared.global [%0], [%1], 16, %2;\n"
                 :: "r"(dst), "l"(src), "r"(sz));
}
__device__ __forceinline__ void cp_commit() {
    asm volatile("cp.async.commit_group;\n");
}
template <int N>
__device__ __forceinline__ void cp_wait() {
    asm volatile("cp.async.wait_group %0;\n" :: "n"(N));
}

// ---------------------------------------------------------------------------
// Edge helpers (edge_index int32; j >= EE are self-loops)
// ---------------------------------------------------------------------------
__device__ __forceinline__ int edge_src(const int* __restrict__ ei, int j) {
    return (j < EE) ? ei[j] : (j - EE);
}
__device__ __forceinline__ int edge_dst(const int* __restrict__ ei, int j) {
    return (j < EE) ? ei[EE + j] : (j - EE);
}

// ---------------------------------------------------------------------------
// prep: pack x / W1^T / W2^T as fp16 pairs; zero o1 K-pad, hist, as1/ad1
// ---------------------------------------------------------------------------
__global__ void prep_kernel(const float* __restrict__ x,
                            const float* __restrict__ W1,
                            const float* __restrict__ W2) {
    int stride = gridDim.x * blockDim.x;
    int tid0 = blockIdx.x * blockDim.x + threadIdx.x;
    for (int i = tid0; i < NN; i += stride) g_hist[i] = 0;
    for (int i = tid0; i < NN * H1; i += stride) { g_as1[i] = 0.f; g_ad1[i] = 0.f; }
    const float2* x2 = (const float2*)x;
    for (int i = tid0; i < NN * K1P; i += stride) {
        float2 v = x2[i];
        g_xp[i] = pack_h16(v.x, v.y);
    }
    for (int i = tid0; i < HID * K1P; i += stride) {   // i = n*64 + kp
        int n = i >> 6, kp = i & 63;
        g_w1[i] = pack_h16(W1[(2 * kp) * HID + n], W1[(2 * kp + 1) * HID + n]);
    }
    for (int i = tid0; i < OUT_CH * K2PAD; i += stride) {  // i = n*672 + kp
        int n = i / K2PAD, kp = i - n * K2PAD;
        uint32_t p = 0;
        if (kp < K2P)
            p = pack_h16(W2[(2 * kp) * OUT_CH + n], W2[(2 * kp + 1) * OUT_CH + n]);
        g_w2[i] = p;
    }
    for (int i = tid0; i < NN * (K2PAD - K2P); i += stride) {
        int n = i / (K2PAD - K2P), kp = K2P + (i - n * (K2PAD - K2P));
        g_o1p[(size_t)n * K2PAD + kp] = 0;
    }
}
__global__ void hist_kernel(const int* __restrict__ ei) {
    int j = blockIdx.x * blockDim.x + threadIdx.x;
    if (j < ETOT) atomicAdd(&g_hist[edge_dst(ei, j)], 1);
}

// ---------------------------------------------------------------------------
// Warp-shuffle scan
// ---------------------------------------------------------------------------
__global__ void scan_kernel() {
    __shared__ int wsum[32];
    int t = threadIdx.x, lane = t & 31, wid = t >> 5;
    if (t == 0) g_rowptr[0] = 0;
    int offset = 0;
    for (int base = 0; base < NN; base += 1024) {
        int i = base + t;
        int v = (i < NN) ? g_hist[i] : 0;
        int incl = v;
        #pragma unroll
        for (int d = 1; d < 32; d <<= 1) {
            int up = __shfl_up_sync(0xFFFFFFFFu, incl, d);
            if (lane >= d) incl += up;
        }
        if (lane == 31) wsum[wid] = incl;
        __syncthreads();
        if (wid == 0) {
            int s = wsum[lane];
            #pragma unroll
            for (int d = 1; d < 32; d <<= 1) {
                int up = __shfl_up_sync(0xFFFFFFFFu, s, d);
                if (lane >= d) s += up;
            }
            wsum[lane] = s;
        }
        __syncthreads();
        int pre = (wid > 0) ? wsum[wid - 1] : 0;
        incl += pre;
        if (i < NN) {
            g_rowptr[i + 1] = offset + incl;
            g_cursor[i]     = offset + incl - v;
        }
        offset += wsum[31];
        __syncthreads();
    }
}
__global__ void scatter_kernel(const int* __restrict__ ei) {
    int j = blockIdx.x * blockDim.x + threadIdx.x;
    if (j >= ETOT) return;
    int d = edge_dst(ei, j);
    int pos = atomicAdd(&g_cursor[d], 1);
    g_srt_src[pos] = edge_src(ei, j);
}

// ---------------------------------------------------------------------------
// gemm1: h1 = x @ W1, all-fp16 single-pass HMMA, 128x128 tiles, LDSM loads.
// Fused epilogue: h1 -> fp16 pairs; attn as1/ad1 via smem stage + atomics.
// ---------------------------------------------------------------------------
#define G1_SMEM (128 * 65 * 4)   // 33280 (stage dominates; k-loop needs 24576)

__global__ void __launch_bounds__(256, 2)
gemm1_kernel(const float* __restrict__ a_src1, const float* __restrict__ a_dst1) {
    constexpr int NT = 8;
    constexpr int KT = IN_CH / 16;             // 8
    constexpr uint32_t A_BUF = 128 * 48;
    constexpr uint32_t B_BUF = 128 * 48;
    constexpr uint32_t OFF_B = 2 * A_BUF;

    extern __shared__ char smem[];
    const uint32_t sb = (uint32_t)__cvta_generic_to_shared(smem);

    const int tid  = threadIdx.x;
    const int wid  = tid >> 5;
    const int lane = tid & 31;
    const int WM = (wid & 3) * 32;
    const int WN = (wid >> 2) * 64;
    const int row0 = blockIdx.y * 128;
    const int col0 = blockIdx.x * 128;

    const int am = tid >> 1, aq = (tid & 1) * 4;
    const int bn = tid >> 1, bq = (tid & 1) * 4;

    const uint32_t lrow = (lane & 7) + ((lane >> 3) & 1) * 8;
    const uint32_t lkoff = (lane >> 4) * 4;

    float acc[2][NT][4];
    #pragma unroll
    for (int mt = 0; mt < 2; mt++)
        #pragma unroll
        for (int nt = 0; nt < NT; nt++)
            #pragma unroll
            for (int q = 0; q < 4; q++) acc[mt][nt][q] = 0.f;

    auto prefetch = [&](int kt, int buf) {
        const int kp0 = kt * 8;
        {
            int gm = row0 + am;
            bool p = gm < NN;
            cp_async16(sb + buf * A_BUF + (am * 12 + aq) * 4,
                       &g_xp[(size_t)(p ? gm : 0) * K1P + kp0 + aq], p);
        }
        {
            int gn = col0 + bn;
            bool p = gn < HID;
            cp_async16(sb + OFF_B + buf * B_BUF + (bn * 12 + bq) * 4,
                       &g_w1[(size_t)(p ? gn : 0) * K1P + kp0 + bq], p);
        }
        cp_commit();
    };

    prefetch(0, 0);

    for (int kt = 0; kt < KT; kt++) {
        const int buf = kt & 1;
        if (kt + 1 < KT) {
            prefetch(kt + 1, buf ^ 1);
            cp_wait<1>();
        } else {
            cp_wait<0>();
        }
        __syncthreads();

        uint32_t ah[2][4], bh[NT][2];
        #pragma unroll
        for (int mt = 0; mt < 2; mt++) {
            uint32_t a = sb + buf * A_BUF + ((WM + mt * 16 + lrow) * 12 + lkoff) * 4;
            ldsm_x4(ah[mt], a);
        }
        #pragma unroll
        for (int ng = 0; ng < NT / 2; ng++) {
            uint32_t a = sb + OFF_B + buf * B_BUF
                       + ((WN + ng * 16 + lrow) * 12 + lkoff) * 4;
            uint32_t rh[4];
            ldsm_x4(rh, a);
            bh[2 * ng][0] = rh[0]; bh[2 * ng + 1][0] = rh[1];
            bh[2 * ng][1] = rh[2]; bh[2 * ng + 1][1] = rh[3];
        }
        #pragma unroll
        for (int mt = 0; mt < 2; mt++)
            #pragma unroll
            for (int nt = 0; nt < NT; nt++)
                mma_f16(acc[mt][nt], ah[mt][0], ah[mt][1], ah[mt][2], ah[mt][3],
                        bh[nt][0], bh[nt][1]);
        __syncthreads();
    }

    // ---- epilogue: pack fp16 pairs, store h1p, stage into smem ----
    const int g = lane & 3;
    const int u = lane >> 2;
    uint32_t* stage = (uint32_t*)smem;   // [128][65] padded
    #pragma unroll
    for (int mt = 0; mt < 2; mt++) {
        int lr0 = WM + mt * 16 + u;
        int lr1 = lr0 + 8;
        int gr0 = row0 + lr0, gr1 = row0 + lr1;
        #pragma unroll
        for (int nt = 0; nt < NT; nt++) {
            int lc = WN + nt * 8 + 2 * g;       // even local col
            int gc = col0 + lc;
            bool cok = gc < HID;
            uint32_t p0 = cok ? pack_h16(acc[mt][nt][0], acc[mt][nt][1]) : 0u;
            uint32_t p1 = cok ? pack_h16(acc[mt][nt][2], acc[mt][nt][3]) : 0u;
            if (cok) {
                if (gr0 < NN) g_h1p[(size_t)gr0 * HIDP + (gc >> 1)] = p0;
                if (gr1 < NN) g_h1p[(size_t)gr1 * HIDP + (gc >> 1)] = p1;
            }
            stage[lr0 * 65 + (lc >> 1)] = p0;
            stage[lr1 * 65 + (lc >> 1)] = p1;
        }
    }
    __syncthreads();

    // ---- attn coefficients: per (row, head) partial dot, atomic accumulate ----
    int hlo = col0 / C1;
    int hhi = (col0 + 127) / C1; if (hhi > H1 - 1) hhi = H1 - 1;
    int nh = hhi - hlo + 1;
    for (int task = tid; task < 128 * nh; task += 256) {
        int row = task & 127;
        int hh  = hlo + (task >> 7);
        int gm = row0 + row;
        if (gm >= NN) continue;
        int cbeg = hh * C1; if (cbeg < col0) cbeg = col0;
        int cend = hh * C1 + C1; if (cend > col0 + 128) cend = col0 + 128;
        float ssum = 0.f, dsum = 0.f;
        for (int pp = cbeg >> 1; pp <= (cend - 1) >> 1; pp++) {
            float2 f = unpack_h16(stage[row * 65 + (pp - (col0 >> 1))]);
            int ce = 2 * pp, co = 2 * pp + 1;
            if (ce >= cbeg && ce < cend) {
                ssum = fmaf(f.x, a_src1[ce], ssum);
                dsum = fmaf(f.x, a_dst1[ce], dsum);
            }
            if (co >= cbeg && co < cend) {
                ssum = fmaf(f.y, a_src1[co], ssum);
                dsum = fmaf(f.y, a_dst1[co], dsum);
            }
        }
        atomicAdd(&g_as1[gm * H1 + hh], ssum);
        atomicAdd(&g_ad1[gm * H1 + hh], dsum);
    }
}

// ---------------------------------------------------------------------------
// gemm2: h2 = o1 @ W2^T. all-fp16 single-pass, 64x128 tiles.
// Fused epilogue: attn2 coefficients as2/ad2 (block holds full h2 rows).
// ---------------------------------------------------------------------------
#define G2_SMEM (64 * 129 * 4)   // 33024 (stage dominates; k-loop needs 18432)

__global__ void __launch_bounds__(256, 2)
gemm2_kernel(const float* __restrict__ a_src2, const float* __restrict__ a_dst2) {
    constexpr int NT = 4;
    constexpr int KT = (2 * K2PAD) / 16;       // 84
    constexpr uint32_t A_BUF = 64 * 48;
    constexpr uint32_t B_BUF = 128 * 48;
    constexpr uint32_t OFF_B = 2 * A_BUF;

    extern __shared__ char smem[];
    const uint32_t sb = (uint32_t)__cvta_generic_to_shared(smem);

    const int tid  = threadIdx.x;
    const int wid  = tid >> 5;
    const int lane = tid & 31;
    const int WM = (wid & 1) * 32;
    const int WN = (wid >> 1) * 32;
    const int row0 = blockIdx.y * 64;

    const int am = tid >> 1, aq = (tid & 1) * 4;
    const bool a_act = tid < 128;
    const int bn = tid >> 1, bq = (tid & 1) * 4;

    const uint32_t lrow = (lane & 7) + ((lane >> 3) & 1) * 8;
    const uint32_t lkoff = (lane >> 4) * 4;

    float acc[2][NT][4];
    #pragma unroll
    for (int mt = 0; mt < 2; mt++)
        #pragma unroll
        for (int nt = 0; nt < NT; nt++)
            #pragma unroll
            for (int q = 0; q < 4; q++) acc[mt][nt][q] = 0.f;

    auto prefetch = [&](int kt, int buf) {
        const int kp0 = kt * 8;
        if (a_act) {
            int gm = row0 + am;
            bool p = gm < NN;
            cp_async16(sb + buf * A_BUF + (am * 12 + aq) * 4,
                       &g_o1p[(size_t)(p ? gm : 0) * K2PAD + kp0 + aq], p);
        }
        cp_async16(sb + OFF_B + buf * B_BUF + (bn * 12 + bq) * 4,
                   &g_w2[(size_t)bn * K2PAD + kp0 + bq], true);
        cp_commit();
    };

    prefetch(0, 0);

    for (int kt = 0; kt < KT; kt++) {
        const int buf = kt & 1;
        if (kt + 1 < KT) {
            prefetch(kt + 1, buf ^ 1);
            cp_wait<1>();
        } else {
            cp_wait<0>();
        }
        __syncthreads();

        uint32_t ah[2][4], bh[NT][2];
        #pragma unroll
        for (int mt = 0; mt < 2; mt++) {
            uint32_t a = sb + buf * A_BUF + ((WM + mt * 16 + lrow) * 12 + lkoff) * 4;
            ldsm_x4(ah[mt], a);
        }
        #pragma unroll
        for (int ng = 0; ng < NT / 2; ng++) {
            uint32_t a = sb + OFF_B + buf * B_BUF
                       + ((WN + ng * 16 + lrow) * 12 + lkoff) * 4;
            uint32_t rh[4];
            ldsm_x4(rh, a);
            bh[2 * ng][0] = rh[0]; bh[2 * ng + 1][0] = rh[1];
            bh[2 * ng][1] = rh[2]; bh[2 * ng + 1][1] = rh[3];
        }
        #pragma unroll
        for (int mt = 0; mt < 2; mt++)
            #pragma unroll
            for (int nt = 0; nt < NT; nt++)
                mma_f16(acc[mt][nt], ah[mt][0], ah[mt][1], ah[mt][2], ah[mt][3],
                        bh[nt][0], bh[nt][1]);
        __syncthreads();
    }

    // ---- epilogue: store h2 + stage fp32 tile in smem for attn2 ----
    const int g = lane & 3;
    const int u = lane >> 2;
    float* stage = (float*)smem;   // [64][129] padded
    #pragma unroll
    for (int mt = 0; mt < 2; mt++) {
        int lr0 = WM + mt * 16 + u;
        int lr1 = lr0 + 8;
        int gr0 = row0 + lr0, gr1 = row0 + lr1;
        #pragma unroll
        for (int nt = 0; nt < NT; nt++) {
            int c = WN + nt * 8 + 2 * g;
            if (gr0 < NN)
                *(float2*)&g_h2[(size_t)gr0 * OUT_CH + c] =
                    make_float2(acc[mt][nt][0], acc[mt][nt][1]);
            if (gr1 < NN)
                *(float2*)&g_h2[(size_t)gr1 * OUT_CH + c] =
                    make_float2(acc[mt][nt][2], acc[mt][nt][3]);
            stage[lr0 * 129 + c]     = acc[mt][nt][0];
            stage[lr0 * 129 + c + 1] = acc[mt][nt][1];
            stage[lr1 * 129 + c]     = acc[mt][nt][2];
            stage[lr1 * 129 + c + 1] = acc[mt][nt][3];
        }
    }
    __syncthreads();

    // ---- attn2: exact per-row dots (full 128 cols in block), no atomics ----
    if (tid < 64) {
        int gm = row0 + tid;
        if (gm < NN) {
            float ssum = 0.f, dsum = 0.f;
            const float* row = &stage[tid * 129];
            #pragma unroll 16
            for (int c = 0; c < OUT_CH; c++) {
                float f = row[c];
                ssum = fmaf(f, a_src2[c], ssum);
                dsum = fmaf(f, a_dst2[c], dsum);
            }
            g_as2[gm] = ssum;
            g_ad2[gm] = dsum;
        }
    }
}

// ---------------------------------------------------------------------------
// Layer-1 aggregation, fully fused softmax (no stats kernel):
// accumulate unnormalized num + den in one pass, normalize at end.
// 324 threads; thread t owns channels [4t, 4t+4); head threads t<36 track den.
// ---------------------------------------------------------------------------
#define AGG1_T 324
#define CE1    9
__global__ void __launch_bounds__(AGG1_T)
agg1_kernel(const float* __restrict__ bias) {
    int n = blockIdx.x;
    int t = threadIdx.x;
    __shared__ float sm_ad[H1], sm_inv[H1];
    __shared__ float w[CE1][H1];
    __shared__ int   ssrc[CE1];

    if (t < H1) sm_ad[t] = g_ad1[n * H1 + t];

    int beg = g_rowptr[n];
    int end = g_rowptr[n + 1];

    const int c0 = 4 * t;
    const int h0 = (c0 + 0) / C1;
    const int h1x = (c0 + 1) / C1;
    const int h2x = (c0 + 2) / C1;
    const int h3x = (c0 + 3) / C1;

    float4 acc = make_float4(0.f, 0.f, 0.f, 0.f);
    float den = 0.f;                       // used by t < H1 only

    for (int j0 = beg; j0 < end; j0 += CE1) {
        int cnt = end - j0; if (cnt > CE1) cnt = CE1;
        if (t < cnt) ssrc[t] = g_srt_src[j0 + t];
        __syncthreads();
        if (t < cnt * H1) {
            int e = t / H1, h = t - e * H1;
            float v = g_as1[ssrc[e] * H1 + h] + sm_ad[h];
            v = (v > 0.f) ? v : 0.2f * v;
            w[e][h] = __expf(v);
        }
        __syncthreads();
        if (t < H1)
            for (int e = 0; e < cnt; e++) den += w[e][t];
        int e = 0;
        for (; e + 2 <= cnt; e += 2) {
            uint2 p0 = *(const uint2*)&g_h1p[(size_t)ssrc[e] * HIDP + 2 * t];
            uint2 p1 = *(const uint2*)&g_h1p[(size_t)ssrc[e + 1] * HIDP + 2 * t];
            float2 a0 = unpack_h16(p0.x), b0 = unpack_h16(p0.y);
            float2 a1 = unpack_h16(p1.x), b1 = unpack_h16(p1.y);
            acc.x = fmaf(a0.x, w[e][h0],  acc.x);
            acc.y = fmaf(a0.y, w[e][h1x], acc.y);
            acc.z = fmaf(b0.x, w[e][h2x], acc.z);
            acc.w = fmaf(b0.y, w[e][h3x], acc.w);
            acc.x = fmaf(a1.x, w[e + 1][h0],  acc.x);
            acc.y = fmaf(a1.y, w[e + 1][h1x], acc.y);
            acc.z = fmaf(b1.x, w[e + 1][h2x], acc.z);
            acc.w = fmaf(b1.y, w[e + 1][h3x], acc.w);
        }
        if (e < cnt) {
            uint2 p0 = *(const uint2*)&g_h1p[(size_t)ssrc[e] * HIDP + 2 * t];
            float2 a0 = unpack_h16(p0.x), b0 = unpack_h16(p0.y);
            acc.x = fmaf(a0.x, w[e][h0],  acc.x);
            acc.y = fmaf(a0.y, w[e][h1x], acc.y);
            acc.z = fmaf(b0.x, w[e][h2x], acc.z);
            acc.w = fmaf(b0.y, w[e][h3x], acc.w);
        }
        __syncthreads();
    }

    if (t < H1) sm_inv[t] = 1.0f / (den + 1e-16f);
    __syncthreads();

    float4 b4 = *(const float4*)&bias[c0];
    float v0 = fmaxf(fmaf(acc.x, sm_inv[h0],  b4.x), 0.f);
    float v1 = fmaxf(fmaf(acc.y, sm_inv[h1x], b4.y), 0.f);
    float v2 = fmaxf(fmaf(acc.z, sm_inv[h2x], b4.z), 0.f);
    float v3 = fmaxf(fmaf(acc.w, sm_inv[h3x], b4.w), 0.f);
    *(uint2*)&g_o1p[(size_t)n * K2PAD + 2 * t] =
        make_uint2(pack_h16(v0, v1), pack_h16(v2, v3));
}

// ---------------------------------------------------------------------------
// Layer-2 aggregation, single pass: num + den together, normalize at end.
// ---------------------------------------------------------------------------
#define CE2 32
__global__ void __launch_bounds__(128)
agg2_kernel(const float* __restrict__ bias, float* __restrict__ out) {
    int n = blockIdx.x;
    int t = threadIdx.x;
    __shared__ float w2[CE2];
    __shared__ int   ssrc2[CE2];

    int beg = g_rowptr[n];
    int end = g_rowptr[n + 1];
    float adn = g_ad2[n];

    float acc = 0.f, den = 0.f;
    for (int j0 = beg; j0 < end; j0 += CE2) {
        int cnt = end - j0; if (cnt > CE2) cnt = CE2;
        if (t < cnt) {
            int s = g_srt_src[j0 + t];
            ssrc2[t] = s;
            float v = g_as2[s] + adn;
            v = (v > 0.f) ? v : 0.2f * v;
            w2[t] = __expf(v);
        }
        __syncthreads();
        for (int e = 0; e < cnt; e++) {
            float we = w2[e];
            den += we;
            acc = fmaf(g_h2[(size_t)ssrc2[e] * OUT_CH + t], we, acc);
        }
        __syncthreads();
    }

    float v = fmaf(acc, 1.0f / (den + 1e-16f), bias[t]);
    out[(size_t)n * OUT_CH + t] = (v > 0.f) ? v : 0.f;
}

// ---------------------------------------------------------------------------
// Launch (gemm1 at slot #4 for the ncu window)
// ---------------------------------------------------------------------------
extern "C" void kernel_launch(void* const* d_in, const int* in_sizes, int n_in,
                              void* d_out, int out_size) {
    const float* x      = (const float*)d_in[0];
    const int*   ei     = (const int*)d_in[1];
    const float* W1     = (const float*)d_in[2];
    const float* a_src1 = (const float*)d_in[3];
    const float* a_dst1 = (const float*)d_in[4];
    const float* b1     = (const float*)d_in[5];
    const float* W2     = (const float*)d_in[6];
    const float* a_src2 = (const float*)d_in[7];
    const float* a_dst2 = (const float*)d_in[8];
    const float* b2     = (const float*)d_in[9];
    float*       out    = (float*)d_out;

    cudaFuncSetAttribute(gemm1_kernel,
                         cudaFuncAttributeMaxDynamicSharedMemorySize, G1_SMEM);
    cudaFuncSetAttribute(gemm2_kernel,
                         cudaFuncAttributeMaxDynamicSharedMemorySize, G2_SMEM);

    prep_kernel<<<512, 256>>>(x, W1, W2);                        // 1
    hist_kernel<<<(ETOT + 255) / 256, 256>>>(ei);                // 2
    scan_kernel<<<1, 1024>>>();                                  // 3
    {
        dim3 grid((HID + 127) / 128, (NN + 127) / 128);          // 4: gemm1 (+attn1)
        gemm1_kernel<<<grid, 256, G1_SMEM>>>(a_src1, a_dst1);
    }
    scatter_kernel<<<(ETOT + 255) / 256, 256>>>(ei);             // 5
    agg1_kernel<<<NN, AGG1_T>>>(b1);                             // 6
    {
        dim3 grid(1, (NN + 63) / 64);                            // 7: gemm2 (+attn2)
        gemm2_kernel<<<grid, 256, G2_SMEM>>>(a_src2, a_dst2);
    }
    agg2_kernel<<<NN, 128>>>(b2, out);                           // 8
}

// round 16
// speedup vs baseline: 1.0350x; 1.0350x over previous
#include <cuda_runtime.h>
#include <cuda_bf16.h>
#include <cuda_fp16.h>
#include <cstdint>

// ---------------------------------------------------------------------------
// Problem constants
// ---------------------------------------------------------------------------
#define NN      20000
#define EE      160000
#define ETOT    (EE + NN)
#define IN_CH   128
#define H1      36
#define C1      36
#define HID     (H1 * C1)   // 1296
#define OUT_CH  128
#define OUTP    (OUT_CH / 2)  // 64 pairs
#define K1P     (IN_CH / 2)   // 64 pairs
#define HIDP    (HID / 2)     // 648 pairs
#define K2P     (HID / 2)     // 648 pairs
#define K2PAD   672           // padded pairs (1344 elems = 84 * 16)

// ---------------------------------------------------------------------------
// Device scratch
// ---------------------------------------------------------------------------
__device__ __align__(16) unsigned int g_h1p[(size_t)NN * HIDP];       // h1 fp16 pairs (52MB)
__device__ __align__(16) unsigned int g_h2p[(size_t)NN * OUTP];       // h2 fp16 pairs (5MB)
__device__ __align__(16) unsigned int g_xp[(size_t)NN * K1P];         // x fp16 pairs [M][64]
__device__ __align__(16) unsigned int g_w1[(size_t)HID * K1P];        // W1^T fp16 [1296][64]
__device__ __align__(16) unsigned int g_w2[(size_t)OUT_CH * K2PAD];   // W2^T fp16 [128][672]
__device__ __align__(16) unsigned int g_o1p[(size_t)NN * K2PAD];      // relu(agg1) fp16 [M][672]
__device__ __align__(16) float g_as1[NN * H1];
__device__ __align__(16) float g_ad1[NN * H1];
__device__ __align__(16) float g_as2[NN];
__device__ __align__(16) float g_ad2[NN];
__device__ int g_hist[NN];
__device__ int g_rowptr[NN + 1];
__device__ int g_cursor[NN];
__device__ int g_srt_src[ETOT];

// ---------------------------------------------------------------------------
// fp16 helpers
// ---------------------------------------------------------------------------
__device__ __forceinline__ uint32_t pack_h16(float a, float b) {
    __half2 t = __floats2half2_rn(a, b);    // .x = a (low half)
    return *reinterpret_cast<uint32_t*>(&t);
}
__device__ __forceinline__ float2 unpack_h16(uint32_t p) {
    __half2 t = *reinterpret_cast<__half2*>(&p);
    return __half22float2(t);
}

__device__ __forceinline__ void mma_f16(float* c,
                                        uint32_t a0, uint32_t a1,
                                        uint32_t a2, uint32_t a3,
                                        uint32_t b0, uint32_t b1) {
    asm volatile(
        "mma.sync.aligned.m16n8k16.row.col.f32.f16.f16.f32 "
        "{%0,%1,%2,%3}, {%4,%5,%6,%7}, {%8,%9}, {%0,%1,%2,%3};\n"
        : "+f"(c[0]), "+f"(c[1]), "+f"(c[2]), "+f"(c[3])
        : "r"(a0), "r"(a1), "r"(a2), "r"(a3), "r"(b0), "r"(b1));
}

__device__ __forceinline__ void ldsm_x4(uint32_t* r, uint32_t addr) {
    asm volatile(
        "ldmatrix.sync.aligned.m8n8.x4.shared.b16 {%0,%1,%2,%3}, [%4];"
        : "=r"(r[0]), "=r"(r[1]), "=r"(r[2]), "=r"(r[3]) : "r"(addr));
}

__device__ __forceinline__ void cp_async16(uint32_t dst, const void* src, bool pred) {
    int sz = pred ? 16 : 0;
    asm volatile("cp.async.ca.shared.global [%0], [%1], 16, %2;\n"
                 :: "r"(dst), "l"(src), "r"(sz));
}
__device__ __forceinline__ void cp_commit() {
    asm volatile("cp.async.commit_group;\n");
}
template <int N>
__device__ __forceinline__ void cp_wait() {
    asm volatile("cp.async.wait_group %0;\n" :: "n"(N));
}

// ---------------------------------------------------------------------------
// Edge helpers (edge_index int32; j >= EE are self-loops)
// ---------------------------------------------------------------------------
__device__ __forceinline__ int edge_src(const int* __restrict__ ei, int j) {
    return (j < EE) ? ei[j] : (j - EE);
}
__device__ __forceinline__ int edge_dst(const int* __restrict__ ei, int j) {
    return (j < EE) ? ei[EE + j] : (j - EE);
}

// ---------------------------------------------------------------------------
// prep: pack x / W1^T / W2^T as fp16 pairs; zero o1 K-pad, hist, as1/ad1
// ---------------------------------------------------------------------------
__global__ void prep_kernel(const float* __restrict__ x,
                            const float* __restrict__ W1,
                            const float* __restrict__ W2) {
    int stride = gridDim.x * blockDim.x;
    int tid0 = blockIdx.x * blockDim.x + threadIdx.x;
    for (int i = tid0; i < NN; i += stride) g_hist[i] = 0;
    for (int i = tid0; i < NN * H1; i += stride) { g_as1[i] = 0.f; g_ad1[i] = 0.f; }
    const float2* x2 = (const float2*)x;
    for (int i = tid0; i < NN * K1P; i += stride) {
        float2 v = x2[i];
        g_xp[i] = pack_h16(v.x, v.y);
    }
    for (int i = tid0; i < HID * K1P; i += stride) {   // i = n*64 + kp
        int n = i >> 6, kp = i & 63;
        g_w1[i] = pack_h16(W1[(2 * kp) * HID + n], W1[(2 * kp + 1) * HID + n]);
    }
    for (int i = tid0; i < OUT_CH * K2PAD; i += stride) {  // i = n*672 + kp
        int n = i / K2PAD, kp = i - n * K2PAD;
        uint32_t p = 0;
        if (kp < K2P)
            p = pack_h16(W2[(2 * kp) * OUT_CH + n], W2[(2 * kp + 1) * OUT_CH + n]);
        g_w2[i] = p;
    }
    for (int i = tid0; i < NN * (K2PAD - K2P); i += stride) {
        int n = i / (K2PAD - K2P), kp = K2P + (i - n * (K2PAD - K2P));
        g_o1p[(size_t)n * K2PAD + kp] = 0;
    }
}
__global__ void hist_kernel(const int* __restrict__ ei) {
    int j = blockIdx.x * blockDim.x + threadIdx.x;
    if (j < ETOT) atomicAdd(&g_hist[edge_dst(ei, j)], 1);
}

// ---------------------------------------------------------------------------
// Warp-shuffle scan
// ---------------------------------------------------------------------------
__global__ void scan_kernel() {
    __shared__ int wsum[32];
    int t = threadIdx.x, lane = t & 31, wid = t >> 5;
    if (t == 0) g_rowptr[0] = 0;
    int offset = 0;
    for (int base = 0; base < NN; base += 1024) {
        int i = base + t;
        int v = (i < NN) ? g_hist[i] : 0;
        int incl = v;
        #pragma unroll
        for (int d = 1; d < 32; d <<= 1) {
            int up = __shfl_up_sync(0xFFFFFFFFu, incl, d);
            if (lane >= d) incl += up;
        }
        if (lane == 31) wsum[wid] = incl;
        __syncthreads();
        if (wid == 0) {
            int s = wsum[lane];
            #pragma unroll
            for (int d = 1; d < 32; d <<= 1) {
                int up = __shfl_up_sync(0xFFFFFFFFu, s, d);
                if (lane >= d) s += up;
            }
            wsum[lane] = s;
        }
        __syncthreads();
        int pre = (wid > 0) ? wsum[wid - 1] : 0;
        incl += pre;
        if (i < NN) {
            g_rowptr[i + 1] = offset + incl;
            g_cursor[i]     = offset + incl - v;
        }
        offset += wsum[31];
        __syncthreads();
    }
}
__global__ void scatter_kernel(const int* __restrict__ ei) {
    int j = blockIdx.x * blockDim.x + threadIdx.x;
    if (j >= ETOT) return;
    int d = edge_dst(ei, j);
    int pos = atomicAdd(&g_cursor[d], 1);
    g_srt_src[pos] = edge_src(ei, j);
}

// ---------------------------------------------------------------------------
// gemm1: h1 = x @ W1, all-fp16 single-pass HMMA, 128x128 tiles, LDSM loads.
// Fused epilogue: h1 -> fp16 pairs; attn as1/ad1 via smem stage + atomics.
// ---------------------------------------------------------------------------
#define G1_SMEM (128 * 65 * 4)   // 33280 (stage dominates; k-loop needs 24576)

__global__ void __launch_bounds__(256, 2)
gemm1_kernel(const float* __restrict__ a_src1, const float* __restrict__ a_dst1) {
    constexpr int NT = 8;
    constexpr int KT = IN_CH / 16;             // 8
    constexpr uint32_t A_BUF = 128 * 48;
    constexpr uint32_t B_BUF = 128 * 48;
    constexpr uint32_t OFF_B = 2 * A_BUF;

    extern __shared__ char smem[];
    const uint32_t sb = (uint32_t)__cvta_generic_to_shared(smem);

    const int tid  = threadIdx.x;
    const int wid  = tid >> 5;
    const int lane = tid & 31;
    const int WM = (wid & 3) * 32;
    const int WN = (wid >> 2) * 64;
    const int row0 = blockIdx.y * 128;
    const int col0 = blockIdx.x * 128;

    const int am = tid >> 1, aq = (tid & 1) * 4;
    const int bn = tid >> 1, bq = (tid & 1) * 4;

    const uint32_t lrow = (lane & 7) + ((lane >> 3) & 1) * 8;
    const uint32_t lkoff = (lane >> 4) * 4;

    float acc[2][NT][4];
    #pragma unroll
    for (int mt = 0; mt < 2; mt++)
        #pragma unroll
        for (int nt = 0; nt < NT; nt++)
            #pragma unroll
            for (int q = 0; q < 4; q++) acc[mt][nt][q] = 0.f;

    auto prefetch = [&](int kt, int buf) {
        const int kp0 = kt * 8;
        {
            int gm = row0 + am;
            bool p = gm < NN;
            cp_async16(sb + buf * A_BUF + (am * 12 + aq) * 4,
                       &g_xp[(size_t)(p ? gm : 0) * K1P + kp0 + aq], p);
        }
        {
            int gn = col0 + bn;
            bool p = gn < HID;
            cp_async16(sb + OFF_B + buf * B_BUF + (bn * 12 + bq) * 4,
                       &g_w1[(size_t)(p ? gn : 0) * K1P + kp0 + bq], p);
        }
        cp_commit();
    };

    prefetch(0, 0);

    for (int kt = 0; kt < KT; kt++) {
        const int buf = kt & 1;
        if (kt + 1 < KT) {
            prefetch(kt + 1, buf ^ 1);
            cp_wait<1>();
        } else {
            cp_wait<0>();
        }
        __syncthreads();

        uint32_t ah[2][4], bh[NT][2];
        #pragma unroll
        for (int mt = 0; mt < 2; mt++) {
            uint32_t a = sb + buf * A_BUF + ((WM + mt * 16 + lrow) * 12 + lkoff) * 4;
            ldsm_x4(ah[mt], a);
        }
        #pragma unroll
        for (int ng = 0; ng < NT / 2; ng++) {
            uint32_t a = sb + OFF_B + buf * B_BUF
                       + ((WN + ng * 16 + lrow) * 12 + lkoff) * 4;
            uint32_t rh[4];
            ldsm_x4(rh, a);
            bh[2 * ng][0] = rh[0]; bh[2 * ng + 1][0] = rh[1];
            bh[2 * ng][1] = rh[2]; bh[2 * ng + 1][1] = rh[3];
        }
        #pragma unroll
        for (int mt = 0; mt < 2; mt++)
            #pragma unroll
            for (int nt = 0; nt < NT; nt++)
                mma_f16(acc[mt][nt], ah[mt][0], ah[mt][1], ah[mt][2], ah[mt][3],
                        bh[nt][0], bh[nt][1]);
        __syncthreads();
    }

    // ---- epilogue: pack fp16 pairs, store h1p, stage into smem ----
    const int g = lane & 3;
    const int u = lane >> 2;
    uint32_t* stage = (uint32_t*)smem;   // [128][65] padded
    #pragma unroll
    for (int mt = 0; mt < 2; mt++) {
        int lr0 = WM + mt * 16 + u;
        int lr1 = lr0 + 8;
        int gr0 = row0 + lr0, gr1 = row0 + lr1;
        #pragma unroll
        for (int nt = 0; nt < NT; nt++) {
            int lc = WN + nt * 8 + 2 * g;       // even local col
            int gc = col0 + lc;
            bool cok = gc < HID;
            uint32_t p0 = cok ? pack_h16(acc[mt][nt][0], acc[mt][nt][1]) : 0u;
            uint32_t p1 = cok ? pack_h16(acc[mt][nt][2], acc[mt][nt][3]) : 0u;
            if (cok) {
                if (gr0 < NN) g_h1p[(size_t)gr0 * HIDP + (gc >> 1)] = p0;
                if (gr1 < NN) g_h1p[(size_t)gr1 * HIDP + (gc >> 1)] = p1;
            }
            stage[lr0 * 65 + (lc >> 1)] = p0;
            stage[lr1 * 65 + (lc >> 1)] = p1;
        }
    }
    __syncthreads();

    // ---- attn coefficients: per (row, head) partial dot, atomic accumulate ----
    int hlo = col0 / C1;
    int hhi = (col0 + 127) / C1; if (hhi > H1 - 1) hhi = H1 - 1;
    int nh = hhi - hlo + 1;
    for (int task = tid; task < 128 * nh; task += 256) {
        int row = task & 127;
        int hh  = hlo + (task >> 7);
        int gm = row0 + row;
        if (gm >= NN) continue;
        int cbeg = hh * C1; if (cbeg < col0) cbeg = col0;
        int cend = hh * C1 + C1; if (cend > col0 + 128) cend = col0 + 128;
        float ssum = 0.f, dsum = 0.f;
        for (int pp = cbeg >> 1; pp <= (cend - 1) >> 1; pp++) {
            float2 f = unpack_h16(stage[row * 65 + (pp - (col0 >> 1))]);
            int ce = 2 * pp, co = 2 * pp + 1;
            if (ce >= cbeg && ce < cend) {
                ssum = fmaf(f.x, a_src1[ce], ssum);
                dsum = fmaf(f.x, a_dst1[ce], dsum);
            }
            if (co >= cbeg && co < cend) {
                ssum = fmaf(f.y, a_src1[co], ssum);
                dsum = fmaf(f.y, a_dst1[co], dsum);
            }
        }
        atomicAdd(&g_as1[gm * H1 + hh], ssum);
        atomicAdd(&g_ad1[gm * H1 + hh], dsum);
    }
}

// ---------------------------------------------------------------------------
// gemm2: h2 = o1 @ W2^T. all-fp16 single-pass, 128x128 tiles (full N in one
// block -> half the blocks / B-traffic of the old 64-row version).
// Fused epilogue: h2 stored as fp16 pairs + attn2 as2/ad2 from fp16 stage.
// ---------------------------------------------------------------------------
#define G2_SMEM (128 * 65 * 4)   // 33280 (stage dominates; k-loop needs 24576)

__global__ void __launch_bounds__(256, 2)
gemm2_kernel(const float* __restrict__ a_src2, const float* __restrict__ a_dst2) {
    constexpr int NT = 8;
    constexpr int KT = (2 * K2PAD) / 16;       // 84
    constexpr uint32_t A_BUF = 128 * 48;
    constexpr uint32_t B_BUF = 128 * 48;
    constexpr uint32_t OFF_B = 2 * A_BUF;

    extern __shared__ char smem[];
    const uint32_t sb = (uint32_t)__cvta_generic_to_shared(smem);

    const int tid  = threadIdx.x;
    const int wid  = tid >> 5;
    const int lane = tid & 31;
    const int WM = (wid & 3) * 32;
    const int WN = (wid >> 2) * 64;
    const int row0 = blockIdx.y * 128;

    const int am = tid >> 1, aq = (tid & 1) * 4;
    const int bn = tid >> 1, bq = (tid & 1) * 4;

    const uint32_t lrow = (lane & 7) + ((lane >> 3) & 1) * 8;
    const uint32_t lkoff = (lane >> 4) * 4;

    float acc[2][NT][4];
    #pragma unroll
    for (int mt = 0; mt < 2; mt++)
        #pragma unroll
        for (int nt = 0; nt < NT; nt++)
            #pragma unroll
            for (int q = 0; q < 4; q++) acc[mt][nt][q] = 0.f;

    auto prefetch = [&](int kt, int buf) {
        const int kp0 = kt * 8;
        {
            int gm = row0 + am;
            bool p = gm < NN;
            cp_async16(sb + buf * A_BUF + (am * 12 + aq) * 4,
                       &g_o1p[(size_t)(p ? gm : 0) * K2PAD + kp0 + aq], p);
        }
        cp_async16(sb + OFF_B + buf * B_BUF + (bn * 12 + bq) * 4,
                   &g_w2[(size_t)bn * K2PAD + kp0 + bq], true);
        cp_commit();
    };

    prefetch(0, 0);

    for (int kt = 0; kt < KT; kt++) {
        const int buf = kt & 1;
        if (kt + 1 < KT) {
            prefetch(kt + 1, buf ^ 1);
            cp_wait<1>();
        } else {
            cp_wait<0>();
        }
        __syncthreads();

        uint32_t ah[2][4], bh[NT][2];
        #pragma unroll
        for (int mt = 0; mt < 2; mt++) {
            uint32_t a = sb + buf * A_BUF + ((WM + mt * 16 + lrow) * 12 + lkoff) * 4;
            ldsm_x4(ah[mt], a);
        }
        #pragma unroll
        for (int ng = 0; ng < NT / 2; ng++) {
            uint32_t a = sb + OFF_B + buf * B_BUF
                       + ((WN + ng * 16 + lrow) * 12 + lkoff) * 4;
            uint32_t rh[4];
            ldsm_x4(rh, a);
            bh[2 * ng][0] = rh[0]; bh[2 * ng + 1][0] = rh[1];
            bh[2 * ng][1] = rh[2]; bh[2 * ng + 1][1] = rh[3];
        }
        #pragma unroll
        for (int mt = 0; mt < 2; mt++)
            #pragma unroll
            for (int nt = 0; nt < NT; nt++)
                mma_f16(acc[mt][nt], ah[mt][0], ah[mt][1], ah[mt][2], ah[mt][3],
                        bh[nt][0], bh[nt][1]);
        __syncthreads();
    }

    // ---- epilogue: pack fp16 pairs, store h2p, stage into smem ----
    const int g = lane & 3;
    const int u = lane >> 2;
    uint32_t* stage = (uint32_t*)smem;   // [128][65] padded
    #pragma unroll
    for (int mt = 0; mt < 2; mt++) {
        int lr0 = WM + mt * 16 + u;
        int lr1 = lr0 + 8;
        int gr0 = row0 + lr0, gr1 = row0 + lr1;
        #pragma unroll
        for (int nt = 0; nt < NT; nt++) {
            int lc = WN + nt * 8 + 2 * g;       // even local col (0..126)
            uint32_t p0 = pack_h16(acc[mt][nt][0], acc[mt][nt][1]);
            uint32_t p1 = pack_h16(acc[mt][nt][2], acc[mt][nt][3]);
            if (gr0 < NN) g_h2p[(size_t)gr0 * OUTP + (lc >> 1)] = p0;
            if (gr1 < NN) g_h2p[(size_t)gr1 * OUTP + (lc >> 1)] = p1;
            stage[lr0 * 65 + (lc >> 1)] = p0;
            stage[lr1 * 65 + (lc >> 1)] = p1;
        }
    }
    __syncthreads();

    // ---- attn2: per-row dots over the staged fp16 row (128 rows, no atomics) ----
    if (tid < 128) {
        int gm = row0 + tid;
        if (gm < NN) {
            float ssum = 0.f, dsum = 0.f;
            const uint32_t* row = &stage[tid * 65];
            #pragma unroll 8
            for (int p = 0; p < OUTP; p++) {
                float2 f = unpack_h16(row[p]);
                ssum = fmaf(f.x, a_src2[2 * p], ssum);
                dsum = fmaf(f.x, a_dst2[2 * p], dsum);
                ssum = fmaf(f.y, a_src2[2 * p + 1], ssum);
                dsum = fmaf(f.y, a_dst2[2 * p + 1], dsum);
            }
            g_as2[gm] = ssum;
            g_ad2[gm] = dsum;
        }
    }
}

// ---------------------------------------------------------------------------
// Layer-1 aggregation, fully fused softmax (num + den in one pass).
// ---------------------------------------------------------------------------
#define AGG1_T 324
#define CE1    9
__global__ void __launch_bounds__(AGG1_T)
agg1_kernel(const float* __restrict__ bias) {
    int n = blockIdx.x;
    int t = threadIdx.x;
    __shared__ float sm_ad[H1], sm_inv[H1];
    __shared__ float w[CE1][H1];
    __shared__ int   ssrc[CE1];

    if (t < H1) sm_ad[t] = g_ad1[n * H1 + t];

    int beg = g_rowptr[n];
    int end = g_rowptr[n + 1];

    const int c0 = 4 * t;
    const int h0 = (c0 + 0) / C1;
    const int h1x = (c0 + 1) / C1;
    const int h2x = (c0 + 2) / C1;
    const int h3x = (c0 + 3) / C1;

    float4 acc = make_float4(0.f, 0.f, 0.f, 0.f);
    float den = 0.f;                       // used by t < H1 only

    for (int j0 = beg; j0 < end; j0 += CE1) {
        int cnt = end - j0; if (cnt > CE1) cnt = CE1;
        if (t < cnt) ssrc[t] = g_srt_src[j0 + t];
        __syncthreads();
        if (t < cnt * H1) {
            int e = t / H1, h = t - e * H1;
            float v = g_as1[ssrc[e] * H1 + h] + sm_ad[h];
            v = (v > 0.f) ? v : 0.2f * v;
            w[e][h] = __expf(v);
        }
        __syncthreads();
        if (t < H1)
            for (int e = 0; e < cnt; e++) den += w[e][t];
        int e = 0;
        for (; e + 2 <= cnt; e += 2) {
            uint2 p0 = *(const uint2*)&g_h1p[(size_t)ssrc[e] * HIDP + 2 * t];
            uint2 p1 = *(const uint2*)&g_h1p[(size_t)ssrc[e + 1] * HIDP + 2 * t];
            float2 a0 = unpack_h16(p0.x), b0 = unpack_h16(p0.y);
            float2 a1 = unpack_h16(p1.x), b1 = unpack_h16(p1.y);
            acc.x = fmaf(a0.x, w[e][h0],  acc.x);
            acc.y = fmaf(a0.y, w[e][h1x], acc.y);
            acc.z = fmaf(b0.x, w[e][h2x], acc.z);
            acc.w = fmaf(b0.y, w[e][h3x], acc.w);
            acc.x = fmaf(a1.x, w[e + 1][h0],  acc.x);
            acc.y = fmaf(a1.y, w[e + 1][h1x], acc.y);
            acc.z = fmaf(b1.x, w[e + 1][h2x], acc.z);
            acc.w = fmaf(b1.y, w[e + 1][h3x], acc.w);
        }
        if (e < cnt) {
            uint2 p0 = *(const uint2*)&g_h1p[(size_t)ssrc[e] * HIDP + 2 * t];
            float2 a0 = unpack_h16(p0.x), b0 = unpack_h16(p0.y);
            acc.x = fmaf(a0.x, w[e][h0],  acc.x);
            acc.y = fmaf(a0.y, w[e][h1x], acc.y);
            acc.z = fmaf(b0.x, w[e][h2x], acc.z);
            acc.w = fmaf(b0.y, w[e][h3x], acc.w);
        }
        __syncthreads();
    }

    if (t < H1) sm_inv[t] = 1.0f / (den + 1e-16f);
    __syncthreads();

    float4 b4 = *(const float4*)&bias[c0];
    float v0 = fmaxf(fmaf(acc.x, sm_inv[h0],  b4.x), 0.f);
    float v1 = fmaxf(fmaf(acc.y, sm_inv[h1x], b4.y), 0.f);
    float v2 = fmaxf(fmaf(acc.z, sm_inv[h2x], b4.z), 0.f);
    float v3 = fmaxf(fmaf(acc.w, sm_inv[h3x], b4.w), 0.f);
    *(uint2*)&g_o1p[(size_t)n * K2PAD + 2 * t] =
        make_uint2(pack_h16(v0, v1), pack_h16(v2, v3));
}

// ---------------------------------------------------------------------------
// Layer-2 aggregation, single pass. 64 threads/node; thread t owns pair t
// (channels 2t, 2t+1). Gathers packed fp16 h2.
// ---------------------------------------------------------------------------
#define CE2 32
__global__ void __launch_bounds__(64)
agg2_kernel(const float* __restrict__ bias, float* __restrict__ out) {
    int n = blockIdx.x;
    int t = threadIdx.x;
    __shared__ float w2[CE2];
    __shared__ int   ssrc2[CE2];

    int beg = g_rowptr[n];
    int end = g_rowptr[n + 1];
    float adn = g_ad2[n];

    float acc0 = 0.f, acc1 = 0.f, den = 0.f;
    for (int j0 = beg; j0 < end; j0 += CE2) {
        int cnt = end - j0; if (cnt > CE2) cnt = CE2;
        if (t < cnt) {
            int s = g_srt_src[j0 + t];
            ssrc2[t] = s;
            float v = g_as2[s] + adn;
            v = (v > 0.f) ? v : 0.2f * v;
            w2[t] = __expf(v);
        }
        __syncthreads();
        for (int e = 0; e < cnt; e++) {
            float we = w2[e];
            den += we;
            float2 f = unpack_h16(g_h2p[(size_t)ssrc2[e] * OUTP + t]);
            acc0 = fmaf(f.x, we, acc0);
            acc1 = fmaf(f.y, we, acc1);
        }
        __syncthreads();
    }

    float inv = 1.0f / (den + 1e-16f);
    float v0 = fmaf(acc0, inv, bias[2 * t]);
    float v1 = fmaf(acc1, inv, bias[2 * t + 1]);
    float2 o = make_float2((v0 > 0.f) ? v0 : 0.f, (v1 > 0.f) ? v1 : 0.f);
    *(float2*)&out[(size_t)n * OUT_CH + 2 * t] = o;
}

// ---------------------------------------------------------------------------
// Launch (gemm1 at slot #4 for the ncu window)
// ---------------------------------------------------------------------------
extern "C" void kernel_launch(void* const* d_in, const int* in_sizes, int n_in,
                              void* d_out, int out_size) {
    const float* x      = (const float*)d_in[0];
    const int*   ei     = (const int*)d_in[1];
    const float* W1     = (const float*)d_in[2];
    const float* a_src1 = (const float*)d_in[3];
    const float* a_dst1 = (const float*)d_in[4];
    const float* b1     = (const float*)d_in[5];
    const float* W2     = (const float*)d_in[6];
    const float* a_src2 = (const float*)d_in[7];
    const float* a_dst2 = (const float*)d_in[8];
    const float* b2     = (const float*)d_in[9];
    float*       out    = (float*)d_out;

    cudaFuncSetAttribute(gemm1_kernel,
                         cudaFuncAttributeMaxDynamicSharedMemorySize, G1_SMEM);
    cudaFuncSetAttribute(gemm2_kernel,
                         cudaFuncAttributeMaxDynamicSharedMemorySize, G2_SMEM);

    prep_kernel<<<512, 256>>>(x, W1, W2);                        // 1
    hist_kernel<<<(ETOT + 255) / 256, 256>>>(ei);                // 2
    scan_kernel<<<1, 1024>>>();                                  // 3
    {
        dim3 grid((HID + 127) / 128, (NN + 127) / 128);          // 4: gemm1 (+attn1)
        gemm1_kernel<<<grid, 256, G1_SMEM>>>(a_src1, a_dst1);
    }
    scatter_kernel<<<(ETOT + 255) / 256, 256>>>(ei);             // 5
    agg1_kernel<<<NN, AGG1_T>>>(b1);                             // 6
    {
        dim3 grid(1, (NN + 127) / 128);                          // 7: gemm2 (+attn2)
        gemm2_kernel<<<grid, 256, G2_SMEM>>>(a_src2, a_dst2);
    }
    agg2_kernel<<<NN, 64>>>(b2, out);                            // 8
}